// round 16
// baseline (speedup 1.0000x reference)
#include <cuda_runtime.h>
#include <cuda_fp16.h>

#define N_NODES 16384
#define SZ 128
#define KPAD 136   // halfs per smem row: 272B, 16B-aligned, conflict-free ldsm
typedef unsigned long long ull;
typedef unsigned int uint32;

__device__ __forceinline__ ull ffma2(ull a, ull b, ull c) {
    ull d;
    asm("fma.rn.f32x2 %0, %1, %2, %3;" : "=l"(d) : "l"(a), "l"(b), "l"(c));
    return d;
}
__device__ __forceinline__ ull pack2(float x, float y) {
    ull d;
    asm("mov.b64 %0, {%1, %2};" : "=l"(d) : "f"(x), "f"(y));
    return d;
}
__device__ __forceinline__ float2 unpack2(ull v) {
    float2 r;
    asm("mov.b64 {%0, %1}, %2;" : "=f"(r.x), "=f"(r.y) : "l"(v));
    return r;
}
__device__ __forceinline__ unsigned h2u(__half2 h) { return *(unsigned*)&h; }

__device__ __forceinline__ void ldsm_x4(uint32& r0, uint32& r1, uint32& r2,
                                        uint32& r3, uint32 addr) {
    asm volatile("ldmatrix.sync.aligned.m8n8.x4.shared.b16 {%0,%1,%2,%3}, [%4];"
                 : "=r"(r0), "=r"(r1), "=r"(r2), "=r"(r3) : "r"(addr));
}
__device__ __forceinline__ void ldsm_x2t(uint32& r0, uint32& r1, uint32 addr) {
    asm volatile("ldmatrix.sync.aligned.m8n8.x2.trans.shared.b16 {%0,%1}, [%2];"
                 : "=r"(r0), "=r"(r1) : "r"(addr));
}
__device__ __forceinline__ void mma_f16(float* c, uint32 a0, uint32 a1,
                                        uint32 a2, uint32 a3,
                                        uint32 b0, uint32 b1) {
    asm volatile(
        "mma.sync.aligned.m16n8k16.row.col.f32.f16.f16.f32 "
        "{%0,%1,%2,%3}, {%4,%5,%6,%7}, {%8,%9}, {%0,%1,%2,%3};"
        : "+f"(c[0]), "+f"(c[1]), "+f"(c[2]), "+f"(c[3])
        : "r"(a0), "r"(a1), "r"(a2), "r"(a3), "r"(b0), "r"(b1));
}

// ---------------- scratch ----------------
__device__ float  g_q[N_NODES * SZ];
__device__ __half g_mk[N_NODES * SZ];
__device__ __half g_mv[N_NODES * SZ];
__device__ __half g_att[N_NODES * SZ];

// ---------------- building blocks ----------------
__device__ __forceinline__ void stage_W_512(const float* __restrict__ W,
                                            __half* Ws, int t) {
#pragma unroll
    for (int i = 0; i < 8; i++) {
        int idx = t + i * 512;
        int r = idx >> 5, c4 = idx & 31;
        float4 v = *(const float4*)(W + r * 128 + c4 * 4);
        uint2 pkt = make_uint2(h2u(__float22half2_rn(make_float2(v.x, v.y))),
                               h2u(__float22half2_rn(make_float2(v.z, v.w))));
        *(uint2*)(Ws + r * KPAD + c4 * 4) = pkt;
    }
}
__device__ __forceinline__ void stage_W_256(const float* __restrict__ W,
                                            __half* Ws, int t) {
#pragma unroll
    for (int i = 0; i < 16; i++) {
        int idx = t + i * 256;
        int r = idx >> 5, c4 = idx & 31;
        float4 v = *(const float4*)(W + r * 128 + c4 * 4);
        uint2 pkt = make_uint2(h2u(__float22half2_rn(make_float2(v.x, v.y))),
                               h2u(__float22half2_rn(make_float2(v.z, v.w))));
        *(uint2*)(Ws + r * KPAD + c4 * 4) = pkt;
    }
}

__device__ __forceinline__ void tile_mma(uint32 a_base, uint32 w_base,
                                         uint32 a_off, uint32 b_krow,
                                         int nc0, float acc[4][4]) {
#pragma unroll
    for (int nt = 0; nt < 4; nt++)
#pragma unroll
        for (int c = 0; c < 4; c++) acc[nt][c] = 0.f;
#pragma unroll
    for (int ks = 0; ks < 8; ks++) {
        const int k0 = ks * 16;
        uint32 a0, a1, a2, a3;
        ldsm_x4(a0, a1, a2, a3, a_base + a_off + k0 * 2);
        uint32 baddr = w_base + ((k0 + b_krow) * KPAD + nc0) * 2;
#pragma unroll
        for (int nt = 0; nt < 4; nt++) {
            uint32 b0, b1;
            ldsm_x2t(b0, b1, baddr + nt * 16);
            mma_f16(acc[nt], a0, a1, a2, a3, b0, b1);
        }
    }
}

template <int RELU, int ADD>
__device__ __forceinline__ void epi_smem(float acc[4][4],
    const float* __restrict__ bias, const float* __restrict__ addg,
    long row0, __half* dst, int ar, int nc0, int lane)
{
    const int g = lane >> 2, tig = lane & 3;
#pragma unroll
    for (int nt = 0; nt < 4; nt++) {
        int col = nc0 + nt * 8 + tig * 2;
        float2 bz = *(const float2*)(bias + col);
        float2 v0 = make_float2(acc[nt][0] + bz.x, acc[nt][1] + bz.y);
        float2 v1 = make_float2(acc[nt][2] + bz.x, acc[nt][3] + bz.y);
        if (RELU) {
            v0.x = fmaxf(v0.x, 0.f); v0.y = fmaxf(v0.y, 0.f);
            v1.x = fmaxf(v1.x, 0.f); v1.y = fmaxf(v1.y, 0.f);
        }
        if (ADD) {
            float2 q0 = *(const float2*)(addg + (row0 + ar + g) * 128 + col);
            float2 q1 = *(const float2*)(addg + (row0 + ar + 8 + g) * 128 + col);
            v0.x += q0.x; v0.y += q0.y;
            v1.x += q1.x; v1.y += q1.y;
        }
        *(__half2*)(dst + (ar + g) * KPAD + col) = __float22half2_rn(v0);
        *(__half2*)(dst + (ar + 8 + g) * KPAD + col) = __float22half2_rn(v1);
    }
}

__device__ __forceinline__ void epi_gmem_h(float acc[4][4], long row0,
                                           __half* __restrict__ C,
                                           int ar, int nc0, int lane)
{
    const int g = lane >> 2, tig = lane & 3;
#pragma unroll
    for (int nt = 0; nt < 4; nt++) {
        int col = nc0 + nt * 8 + tig * 2;
        long r0 = row0 + ar + g, r1 = r0 + 8;
        *(__half2*)(C + r0 * 128 + col) =
            __float22half2_rn(make_float2(acc[nt][0], acc[nt][1]));
        *(__half2*)(C + r1 * 128 + col) =
            __float22half2_rn(make_float2(acc[nt][2], acc[nt][3]));
    }
}

__device__ __forceinline__ void epi_gmem_f(float acc[4][4],
    const float* __restrict__ bias, long row0, float* __restrict__ C,
    int ar, int nc0, int lane)
{
    const int g = lane >> 2, tig = lane & 3;
#pragma unroll
    for (int nt = 0; nt < 4; nt++) {
        int col = nc0 + nt * 8 + tig * 2;
        long r0 = row0 + ar + g, r1 = r0 + 8;
        float2 bz = *(const float2*)(bias + col);
        *(float2*)(C + r0 * 128 + col) =
            make_float2(acc[nt][0] + bz.x, acc[nt][1] + bz.y);
        *(float2*)(C + r1 * 128 + col) =
            make_float2(acc[nt][2] + bz.x, acc[nt][3] + bz.y);
    }
}

// ------- PERSISTENT MLP v2 (R15-proven, unchanged) --------------------------
#define NBAR() asm volatile("bar.sync %0, 256;" :: "r"(barid) : "memory")

__global__ __launch_bounds__(512) void mlp_persistent(
    const float* __restrict__ F,
    const float* __restrict__ Wq, const float* __restrict__ bq,
    const float* __restrict__ W1, const float* __restrict__ b1,
    const float* __restrict__ W2, const float* __restrict__ b2,
    const float* __restrict__ W3, const float* __restrict__ b3,
    const float* __restrict__ enc,
    const float* __restrict__ Wk, const float* __restrict__ Wv,
    float* __restrict__ q, __half* __restrict__ mk, __half* __restrict__ mv)
{
    extern __shared__ __half sm[];
    const int t = threadIdx.x;
    const int wg = t >> 8;
    const int wt = t & 255;
    __half* buf = sm + wg * 32 * KPAD;
    __half* WS = sm + 64 * KPAD;
    const int lane = t & 31;
    const int wiw = wt >> 5;
    const int mw = wiw & 1, nw = wiw >> 1;
    const int ar = mw * 16, nc0 = nw * 32;
    const int barid = 1 + wg;

    const uint32 a_base = (uint32)__cvta_generic_to_shared(buf);
    const int lrow = lane & 7, quad = lane >> 3;
    const uint32 a_off =
        ((uint32)(ar + lrow + ((quad & 1) << 3)) * KPAD + ((quad & 2) << 2)) * 2;
    const uint32 b_krow = (lane & 7) + (lane & 8);

    stage_W_512(Wq, WS + 0 * 128 * KPAD, t);
    stage_W_512(W1, WS + 1 * 128 * KPAD, t);
    stage_W_512(W2, WS + 2 * 128 * KPAD, t);
    stage_W_512(W3, WS + 3 * 128 * KPAD, t);
    stage_W_512(Wk, WS + 4 * 128 * KPAD, t);
    stage_W_512(Wv, WS + 5 * 128 * KPAD, t);
    uint32 wb[6];
#pragma unroll
    for (int i = 0; i < 6; i++)
        wb[i] = (uint32)__cvta_generic_to_shared(WS + i * 128 * KPAD);
    __syncthreads();

    float acc[4][4];
#pragma unroll 1
    for (int round = 0; round < 2; round++) {
        const long tile = (long)blockIdx.x * 2 + wg + 296 * round;
        if (tile >= 512) break;
        const long row0 = tile * 32;

#pragma unroll
        for (int i = 0; i < 4; i++) {
            int idx = wt + i * 256;
            int r = idx >> 5, c4 = idx & 31;
            float4 v = *(const float4*)(F + (row0 + r) * 128 + c4 * 4);
            uint2 raw = make_uint2(
                h2u(__float22half2_rn(make_float2(v.x, v.y))),
                h2u(__float22half2_rn(make_float2(v.z, v.w))));
            *(uint2*)(buf + r * KPAD + c4 * 4) = raw;
        }
        NBAR();

        tile_mma(a_base, wb[0], a_off, b_krow, nc0, acc);
        epi_gmem_f(acc, bq, row0, q, ar, nc0, lane);
        NBAR();

        {
            const __half2 z2 = __float2half2_rn(0.f);
#pragma unroll
            for (int i = 0; i < 2; i++) {
                int idx = wt + i * 256;
                int r = idx >> 4, c8 = idx & 15;
                __half2* p = (__half2*)(buf + r * KPAD + c8 * 8);
                p[0] = __hmax2(p[0], z2);
                p[1] = __hmax2(p[1], z2);
                p[2] = __hmax2(p[2], z2);
                p[3] = __hmax2(p[3], z2);
            }
        }
        NBAR();

        tile_mma(a_base, wb[1], a_off, b_krow, nc0, acc);
        NBAR();
        epi_smem<1, 0>(acc, b1, nullptr, row0, buf, ar, nc0, lane);
        NBAR();

        tile_mma(a_base, wb[2], a_off, b_krow, nc0, acc);
        NBAR();
        epi_smem<1, 0>(acc, b2, nullptr, row0, buf, ar, nc0, lane);
        NBAR();

        tile_mma(a_base, wb[3], a_off, b_krow, nc0, acc);
        NBAR();
        epi_smem<1, 1>(acc, b3, enc, row0, buf, ar, nc0, lane);
        NBAR();

        tile_mma(a_base, wb[4], a_off, b_krow, nc0, acc);
        epi_gmem_h(acc, row0, mk, ar, nc0, lane);
        tile_mma(a_base, wb[5], a_off, b_krow, nc0, acc);
        epi_gmem_h(acc, row0, mv, ar, nc0, lane);
        NBAR();
    }
}

// ------- out-projection (R15-proven, unchanged) -----------------------------
__global__ __launch_bounds__(256) void tgemm_out(
    const __half* __restrict__ A, const float* __restrict__ W,
    const float* __restrict__ bias, const float* __restrict__ add,
    float* __restrict__ C)
{
    extern __shared__ __half sm[];
    __half* As = sm;
    __half* Ws = sm + 32 * KPAD;
    const int t = threadIdx.x;
    const int lane = t & 31, w = t >> 5;
    const int mw = w & 1, nw = w >> 1;
    const long row0 = (long)blockIdx.x * 32;

#pragma unroll
    for (int i = 0; i < 2; i++) {
        int idx = t + i * 256;
        int r = idx >> 4, c8 = idx & 15;
        uint4 v = *(const uint4*)(A + (row0 + r) * 128 + c8 * 8);
        *(uint4*)(As + r * KPAD + c8 * 8) = v;
    }
    stage_W_256(W, Ws, t);
    __syncthreads();

    const int ar = mw * 16, nc0 = nw * 32;
    const uint32 a_base = (uint32)__cvta_generic_to_shared(As);
    const uint32 w_base = (uint32)__cvta_generic_to_shared(Ws);
    const int lrow = lane & 7, quad = lane >> 3;
    const uint32 a_off =
        ((uint32)(ar + lrow + ((quad & 1) << 3)) * KPAD + ((quad & 2) << 2)) * 2;
    const uint32 b_krow = (lane & 7) + (lane & 8);

    float acc[4][4];
    tile_mma(a_base, w_base, a_off, b_krow, nc0, acc);

    const int g = lane >> 2, tig = lane & 3;
#pragma unroll
    for (int nt = 0; nt < 4; nt++) {
        int col = nc0 + nt * 8 + tig * 2;
        long r0 = row0 + ar + g, r1 = r0 + 8;
        float2 bz = *(const float2*)(bias + col);
        float2 a0 = *(const float2*)(add + r0 * 128 + col);
        float2 a1 = *(const float2*)(add + r1 * 128 + col);
        *(float2*)(C + r0 * 128 + col) =
            make_float2(acc[nt][0] + bz.x + a0.x, acc[nt][1] + bz.y + a0.y);
        *(float2*)(C + r1 * 128 + col) =
            make_float2(acc[nt][2] + bz.x + a1.x, acc[nt][3] + bz.y + a1.y);
    }
}

// ---------------- attention: 2 warps/node + register PREFETCH of gathers ----
struct __align__(16) NodeSmem {
    __half dist[32 * 36];
    __half seq[32 * 20];
    float ud_t[32 * 8];
    float us_t[16 * 8];
    float c0[8];
    float lgk[32 * 10];
    float sd[2][256];
    float ss[2][128];
    float accp[2][128];
    int   jb[32];
};

__global__ __launch_bounds__(128) void attn_kernel(
    const float* __restrict__ dist_g, const float* __restrict__ seq_g,
    const int* __restrict__ idx, const float* __restrict__ qg,
    const __half* __restrict__ mkh, const __half* __restrict__ mvh,
    const float* __restrict__ Wk, const float* __restrict__ bk,
    const float* __restrict__ Wv, const float* __restrict__ bv,
    __half* __restrict__ att_out)
{
    __shared__ NodeSmem S[2];
    const int lane = threadIdx.x & 31;
    const int w = threadIdx.x >> 5;
    const int half = w & 1;
    NodeSmem& s = S[w >> 1];
    const int n = blockIdx.x * 2 + (w >> 1);

    const float4 qv = ((const float4*)(qg + (long)n * 128))[lane];

    // ---- Phase A: staging (jb by half0; dist/seq split)
    if (half == 0) {
        s.jb[lane] = idx[n * 32 + lane];
        const float4* dg = (const float4*)(dist_g + (long)n * 1024);
#pragma unroll
        for (int it = 0; it < 4; it++) {
            int i4 = it * 32 + lane;
            float4 v = dg[i4];
            uint2 h;
            h.x = h2u(__float22half2_rn(make_float2(v.x, v.y)));
            h.y = h2u(__float22half2_rn(make_float2(v.z, v.w)));
            *(uint2*)(s.dist + (i4 >> 3) * 36 + (i4 & 7) * 4) = h;
        }
    } else {
        const float4* dg = (const float4*)(dist_g + (long)n * 1024);
#pragma unroll
        for (int it = 4; it < 8; it++) {
            int i4 = it * 32 + lane;
            float4 v = dg[i4];
            uint2 h;
            h.x = h2u(__float22half2_rn(make_float2(v.x, v.y)));
            h.y = h2u(__float22half2_rn(make_float2(v.z, v.w)));
            *(uint2*)(s.dist + (i4 >> 3) * 36 + (i4 & 7) * 4) = h;
        }
        const float4* sg = (const float4*)(seq_g + (long)n * 512);
#pragma unroll
        for (int it = 0; it < 4; it++) {
            int i4 = it * 32 + lane;
            float4 v = sg[i4];
            uint2 h;
            h.x = h2u(__float22half2_rn(make_float2(v.x, v.y)));
            h.y = h2u(__float22half2_rn(make_float2(v.z, v.w)));
            *(uint2*)(s.seq + (i4 >> 2) * 20 + (i4 & 3) * 4) = h;
        }
    }
    __syncthreads();   // jb + dist + seq visible to both warps

    // ---- PREFETCH: issue all 16 mk gather rows for this half NOW;
    //      the Wk fold below hides their L2 latency.
    uint2 mkp[16];
#pragma unroll
    for (int kk = 0; kk < 16; kk++) {
        int j = s.jb[half * 16 + kk];
        mkp[kk] = *(const uint2*)(mkh + (long)j * 128 + lane * 4);
    }

    // ---- Phase B: fold rows split 24/24 (+bias on half 0)
    const int h4 = lane >> 2;
#pragma unroll 8
    for (int rr = 0; rr < 24; rr++) {
        int r = half * 24 + rr;
        float4 wv = *(const float4*)(Wk + (long)(128 + r) * 128 + lane * 4);
        float p = wv.x * qv.x + wv.y * qv.y + wv.z * qv.z + wv.w * qv.w;
        p += __shfl_xor_sync(~0u, p, 1);
        p += __shfl_xor_sync(~0u, p, 2);
        if ((lane & 3) == 0) {
            if (r < 32) s.ud_t[r * 8 + h4] = p;
            else        s.us_t[(r - 32) * 8 + h4] = p;
        }
    }
    if (half == 0) {
        float4 wv = *(const float4*)(bk + lane * 4);
        float p = wv.x * qv.x + wv.y * qv.y + wv.z * qv.z + wv.w * qv.w;
        p += __shfl_xor_sync(~0u, p, 1);
        p += __shfl_xor_sync(~0u, p, 2);
        if ((lane & 3) == 0) s.c0[h4] = p;
    }

    // ---- Phase C1: consume prefetched mk rows (pure register math)
#pragma unroll
    for (int kk = 0; kk < 16; kk++) {
        int k = half * 16 + kk;
        float2 f0 = __half22float2(*(__half2*)&mkp[kk].x);
        float2 f1 = __half22float2(*(__half2*)&mkp[kk].y);
        float p = f0.x * qv.x + f0.y * qv.y + f1.x * qv.z + f1.y * qv.w;
        p += __shfl_xor_sync(~0u, p, 1);
        p += __shfl_xor_sync(~0u, p, 2);
        if ((lane & 3) == 0) s.lgk[k * 10 + h4] = p;
    }

    // ---- PREFETCH: issue all 16 mv gather rows; C2+softmax hides latency.
    uint2 mvp[16];
#pragma unroll
    for (int kk = 0; kk < 16; kk++) {
        int j = s.jb[half * 16 + kk];
        mvp[kk] = *(const uint2*)(mvh + (long)j * 128 + lane * 4);
    }
    __syncthreads();   // lgk (mk part) + ud_t/us_t/c0 visible

    // ---- Phase C2 + softmax: each warp owns 4 heads
    {
        ull acc01 = 0ull, acc23 = 0ull;
        const __half* drow = s.dist + lane * 36;
#pragma unroll
        for (int i = 0; i < 8; i++) {
            uint2 hv = *(const uint2*)(drow + i * 4);
            float2 f0 = __half22float2(*(__half2*)&hv.x);
            float2 f1 = __half22float2(*(__half2*)&hv.y);
            float dv[4] = {f0.x, f0.y, f1.x, f1.y};
#pragma unroll
            for (int e = 0; e < 4; e++) {
                int d = i * 4 + e;
                ull dv2 = pack2(dv[e], dv[e]);
                const ull* u = (const ull*)(s.ud_t + d * 8 + half * 4);
                acc01 = ffma2(u[0], dv2, acc01);
                acc23 = ffma2(u[1], dv2, acc23);
            }
        }
        const __half* srow = s.seq + lane * 20;
#pragma unroll
        for (int i = 0; i < 4; i++) {
            uint2 hv = *(const uint2*)(srow + i * 4);
            float2 f0 = __half22float2(*(__half2*)&hv.x);
            float2 f1 = __half22float2(*(__half2*)&hv.y);
            float sv[4] = {f0.x, f0.y, f1.x, f1.y};
#pragma unroll
            for (int e = 0; e < 4; e++) {
                int si = i * 4 + e;
                ull sv2 = pack2(sv[e], sv[e]);
                const ull* u = (const ull*)(s.us_t + si * 8 + half * 4);
                acc01 = ffma2(u[0], sv2, acc01);
                acc23 = ffma2(u[1], sv2, acc23);
            }
        }
        float2 pA = unpack2(acc01), pB = unpack2(acc23);
        float pa[4] = {pA.x, pA.y, pB.x, pB.y};
#pragma unroll
        for (int hh = 0; hh < 4; hh++) {
            int h = half * 4 + hh;
            float lg = 0.25f * (s.lgk[lane * 10 + h] + pa[hh] + s.c0[h]);
            float m = lg;
#pragma unroll
            for (int o = 16; o > 0; o >>= 1)
                m = fmaxf(m, __shfl_xor_sync(~0u, m, o));
            float e = __expf(lg - m);
            float sm = e;
#pragma unroll
            for (int o = 16; o > 0; o >>= 1)
                sm += __shfl_xor_sync(~0u, sm, o);
            s.lgk[lane * 10 + h] = e / sm;
        }
    }
    __syncthreads();   // all attn weights final

    // ---- Phase D: consume prefetched mv rows + weighted sums
    {
        const int sidx = lane & 15;
        float4 acc = make_float4(0.f, 0.f, 0.f, 0.f);
        ull sdl2[4] = {0ull, 0ull, 0ull, 0ull};
        float ssl[4] = {0.f, 0.f, 0.f, 0.f};
#pragma unroll 4
        for (int kk = 0; kk < 16; kk++) {
            int k = half * 16 + kk;
            float a = s.lgk[k * 10 + h4];
            float2 f0 = __half22float2(*(__half2*)&mvp[kk].x);
            float2 f1 = __half22float2(*(__half2*)&mvp[kk].y);
            acc.x += a * f0.x; acc.y += a * f0.y;
            acc.z += a * f1.x; acc.w += a * f1.y;
            float dv = __half2float(s.dist[k * 36 + lane]);
            ull dv2 = pack2(dv, dv);
            const ull* ap = (const ull*)(s.lgk + k * 10);
#pragma unroll
            for (int r = 0; r < 4; r++) sdl2[r] = ffma2(ap[r], dv2, sdl2[r]);
            float sv = __half2float(s.seq[k * 20 + sidx]);
#pragma unroll
            for (int r = 0; r < 4; r++) {
                int h2 = (lane >> 4) + 2 * r;
                ssl[r] += s.lgk[k * 10 + h2] * sv;
            }
        }
        *(float4*)(s.accp[half] + lane * 4) = acc;
#pragma unroll
        for (int r = 0; r < 4; r++) {
            float2 p = unpack2(sdl2[r]);
            s.sd[half][(2 * r) * 32 + lane] = p.x;
            s.sd[half][(2 * r + 1) * 32 + lane] = p.y;
        }
#pragma unroll
        for (int r = 0; r < 4; r++) s.ss[half][lane + 32 * r] = ssl[r];
    }
    __syncthreads();

    // ---- Phase D2: combine + project; this warp owns dims [half*64, +64)
    {
        const int i0 = half * 64 + lane * 2;
        const int h = i0 >> 4;
        float2 a0 = *(const float2*)(s.accp[0] + i0);
        float2 a1 = *(const float2*)(s.accp[1] + i0);
        float2 bb = *(const float2*)(bv + i0);
        ull o = pack2(a0.x + a1.x + bb.x, a0.y + a1.y + bb.y);
#pragma unroll 8
        for (int d = 0; d < 32; d++) {
            float sdv = s.sd[0][h * 32 + d] + s.sd[1][h * 32 + d];
            ull wv = *(const ull*)(Wv + (long)(128 + d) * 128 + i0);
            o = ffma2(wv, pack2(sdv, sdv), o);
        }
#pragma unroll 8
        for (int j2 = 0; j2 < 16; j2++) {
            int si = (h & 1) * 16 + j2 + 32 * (h >> 1);
            float ssv = s.ss[0][si] + s.ss[1][si];
            ull wv = *(const ull*)(Wv + (long)(160 + j2) * 128 + i0);
            o = ffma2(wv, pack2(ssv, ssv), o);
        }
        float2 po = unpack2(o);
        *(__half2*)(att_out + (long)n * 128 + i0) = __float22half2_rn(po);
    }
}

// ---------------- launch ----------------
#define TG_SMEM ((32 + 128) * KPAD * 2)            // 43,520 B
#define PERS_SMEM ((64 + 6 * 128) * KPAD * 2)      // 226,304 B

extern "C" void kernel_launch(void* const* d_in, const int* in_sizes, int n_in,
                              void* d_out, int out_size)
{
    const float* features = (const float*)d_in[0];
    const float* distances = (const float*)d_in[1];
    const float* sequence = (const float*)d_in[2];
    const float* encoder = (const float*)d_in[3];
    const int*   idx = (const int*)d_in[4];
    const float* W1 = (const float*)d_in[5];
    const float* b1 = (const float*)d_in[6];
    const float* W2 = (const float*)d_in[7];
    const float* b2 = (const float*)d_in[8];
    const float* W3 = (const float*)d_in[9];
    const float* b3 = (const float*)d_in[10];
    const float* Wq = (const float*)d_in[11];
    const float* bq = (const float*)d_in[12];
    const float* Wk = (const float*)d_in[13];
    const float* bk = (const float*)d_in[14];
    const float* Wv = (const float*)d_in[15];
    const float* bv = (const float*)d_in[16];
    const float* Wo = (const float*)d_in[17];
    const float* bo = (const float*)d_in[18];

    float *q;
    __half *mk, *mv, *att;
    cudaGetSymbolAddress((void**)&q, g_q);
    cudaGetSymbolAddress((void**)&mk, g_mk);
    cudaGetSymbolAddress((void**)&mv, g_mv);
    cudaGetSymbolAddress((void**)&att, g_att);

    static int smem_set = 0;
    if (!smem_set) {
        cudaFuncSetAttribute(mlp_persistent,
            cudaFuncAttributeMaxDynamicSharedMemorySize, PERS_SMEM);
        smem_set = 1;
    }

    mlp_persistent<<<148, 512, PERS_SMEM>>>(features, Wq, bq, W1, b1,
                                            W2, b2, W3, b3, encoder,
                                            Wk, Wv, q, mk, mv);
    attn_kernel<<<N_NODES / 2, 128>>>(distances, sequence, idx,
                                      q, mk, mv, Wk, bk, Wv, bv, att);
    tgemm_out<<<N_NODES / 32, 256, TG_SMEM>>>(att, Wo, bo, features,
                                              (float*)d_out);
}

// round 17
// speedup vs baseline: 1.0695x; 1.0695x over previous
#include <cuda_runtime.h>
#include <cuda_fp16.h>

#define N_NODES 16384
#define SZ 128
#define KPAD 136   // halfs per smem row: 272B, 16B-aligned, conflict-free ldsm
typedef unsigned long long ull;
typedef unsigned int uint32;

__device__ __forceinline__ ull ffma2(ull a, ull b, ull c) {
    ull d;
    asm("fma.rn.f32x2 %0, %1, %2, %3;" : "=l"(d) : "l"(a), "l"(b), "l"(c));
    return d;
}
__device__ __forceinline__ ull pack2(float x, float y) {
    ull d;
    asm("mov.b64 %0, {%1, %2};" : "=l"(d) : "f"(x), "f"(y));
    return d;
}
__device__ __forceinline__ float2 unpack2(ull v) {
    float2 r;
    asm("mov.b64 {%0, %1}, %2;" : "=f"(r.x), "=f"(r.y) : "l"(v));
    return r;
}
__device__ __forceinline__ unsigned h2u(__half2 h) { return *(unsigned*)&h; }

__device__ __forceinline__ void ldsm_x4(uint32& r0, uint32& r1, uint32& r2,
                                        uint32& r3, uint32 addr) {
    asm volatile("ldmatrix.sync.aligned.m8n8.x4.shared.b16 {%0,%1,%2,%3}, [%4];"
                 : "=r"(r0), "=r"(r1), "=r"(r2), "=r"(r3) : "r"(addr));
}
__device__ __forceinline__ void ldsm_x2t(uint32& r0, uint32& r1, uint32 addr) {
    asm volatile("ldmatrix.sync.aligned.m8n8.x2.trans.shared.b16 {%0,%1}, [%2];"
                 : "=r"(r0), "=r"(r1) : "r"(addr));
}
__device__ __forceinline__ void mma_f16(float* c, uint32 a0, uint32 a1,
                                        uint32 a2, uint32 a3,
                                        uint32 b0, uint32 b1) {
    asm volatile(
        "mma.sync.aligned.m16n8k16.row.col.f32.f16.f16.f32 "
        "{%0,%1,%2,%3}, {%4,%5,%6,%7}, {%8,%9}, {%0,%1,%2,%3};"
        : "+f"(c[0]), "+f"(c[1]), "+f"(c[2]), "+f"(c[3])
        : "r"(a0), "r"(a1), "r"(a2), "r"(a3), "r"(b0), "r"(b1));
}

// ---------------- scratch ----------------
__device__ float  g_q[N_NODES * SZ];
__device__ __half g_mk[N_NODES * SZ];
__device__ __half g_mv[N_NODES * SZ];
__device__ __half g_att[N_NODES * SZ];

// ---------------- building blocks ----------------
__device__ __forceinline__ void stage_W_512(const float* __restrict__ W,
                                            __half* Ws, int t) {
#pragma unroll
    for (int i = 0; i < 8; i++) {
        int idx = t + i * 512;
        int r = idx >> 5, c4 = idx & 31;
        float4 v = *(const float4*)(W + r * 128 + c4 * 4);
        uint2 pkt = make_uint2(h2u(__float22half2_rn(make_float2(v.x, v.y))),
                               h2u(__float22half2_rn(make_float2(v.z, v.w))));
        *(uint2*)(Ws + r * KPAD + c4 * 4) = pkt;
    }
}
__device__ __forceinline__ void stage_W_256(const float* __restrict__ W,
                                            __half* Ws, int t) {
#pragma unroll
    for (int i = 0; i < 16; i++) {
        int idx = t + i * 256;
        int r = idx >> 5, c4 = idx & 31;
        float4 v = *(const float4*)(W + r * 128 + c4 * 4);
        uint2 pkt = make_uint2(h2u(__float22half2_rn(make_float2(v.x, v.y))),
                               h2u(__float22half2_rn(make_float2(v.z, v.w))));
        *(uint2*)(Ws + r * KPAD + c4 * 4) = pkt;
    }
}

__device__ __forceinline__ void tile_mma(uint32 a_base, uint32 w_base,
                                         uint32 a_off, uint32 b_krow,
                                         int nc0, float acc[4][4]) {
#pragma unroll
    for (int nt = 0; nt < 4; nt++)
#pragma unroll
        for (int c = 0; c < 4; c++) acc[nt][c] = 0.f;
#pragma unroll
    for (int ks = 0; ks < 8; ks++) {
        const int k0 = ks * 16;
        uint32 a0, a1, a2, a3;
        ldsm_x4(a0, a1, a2, a3, a_base + a_off + k0 * 2);
        uint32 baddr = w_base + ((k0 + b_krow) * KPAD + nc0) * 2;
#pragma unroll
        for (int nt = 0; nt < 4; nt++) {
            uint32 b0, b1;
            ldsm_x2t(b0, b1, baddr + nt * 16);
            mma_f16(acc[nt], a0, a1, a2, a3, b0, b1);
        }
    }
}

template <int RELU, int ADD>
__device__ __forceinline__ void epi_smem(float acc[4][4],
    const float* __restrict__ bias, const float* __restrict__ addg,
    long row0, __half* dst, int ar, int nc0, int lane)
{
    const int g = lane >> 2, tig = lane & 3;
#pragma unroll
    for (int nt = 0; nt < 4; nt++) {
        int col = nc0 + nt * 8 + tig * 2;
        float2 bz = *(const float2*)(bias + col);
        float2 v0 = make_float2(acc[nt][0] + bz.x, acc[nt][1] + bz.y);
        float2 v1 = make_float2(acc[nt][2] + bz.x, acc[nt][3] + bz.y);
        if (RELU) {
            v0.x = fmaxf(v0.x, 0.f); v0.y = fmaxf(v0.y, 0.f);
            v1.x = fmaxf(v1.x, 0.f); v1.y = fmaxf(v1.y, 0.f);
        }
        if (ADD) {
            float2 q0 = *(const float2*)(addg + (row0 + ar + g) * 128 + col);
            float2 q1 = *(const float2*)(addg + (row0 + ar + 8 + g) * 128 + col);
            v0.x += q0.x; v0.y += q0.y;
            v1.x += q1.x; v1.y += q1.y;
        }
        *(__half2*)(dst + (ar + g) * KPAD + col) = __float22half2_rn(v0);
        *(__half2*)(dst + (ar + 8 + g) * KPAD + col) = __float22half2_rn(v1);
    }
}

__device__ __forceinline__ void epi_gmem_h(float acc[4][4], long row0,
                                           __half* __restrict__ C,
                                           int ar, int nc0, int lane)
{
    const int g = lane >> 2, tig = lane & 3;
#pragma unroll
    for (int nt = 0; nt < 4; nt++) {
        int col = nc0 + nt * 8 + tig * 2;
        long r0 = row0 + ar + g, r1 = r0 + 8;
        *(__half2*)(C + r0 * 128 + col) =
            __float22half2_rn(make_float2(acc[nt][0], acc[nt][1]));
        *(__half2*)(C + r1 * 128 + col) =
            __float22half2_rn(make_float2(acc[nt][2], acc[nt][3]));
    }
}

__device__ __forceinline__ void epi_gmem_f(float acc[4][4],
    const float* __restrict__ bias, long row0, float* __restrict__ C,
    int ar, int nc0, int lane)
{
    const int g = lane >> 2, tig = lane & 3;
#pragma unroll
    for (int nt = 0; nt < 4; nt++) {
        int col = nc0 + nt * 8 + tig * 2;
        long r0 = row0 + ar + g, r1 = r0 + 8;
        float2 bz = *(const float2*)(bias + col);
        *(float2*)(C + r0 * 128 + col) =
            make_float2(acc[nt][0] + bz.x, acc[nt][1] + bz.y);
        *(float2*)(C + r1 * 128 + col) =
            make_float2(acc[nt][2] + bz.x, acc[nt][3] + bz.y);
    }
}

// ------- PERSISTENT MLP v2 (R15-proven, unchanged) --------------------------
#define NBAR() asm volatile("bar.sync %0, 256;" :: "r"(barid) : "memory")

__global__ __launch_bounds__(512) void mlp_persistent(
    const float* __restrict__ F,
    const float* __restrict__ Wq, const float* __restrict__ bq,
    const float* __restrict__ W1, const float* __restrict__ b1,
    const float* __restrict__ W2, const float* __restrict__ b2,
    const float* __restrict__ W3, const float* __restrict__ b3,
    const float* __restrict__ enc,
    const float* __restrict__ Wk, const float* __restrict__ Wv,
    float* __restrict__ q, __half* __restrict__ mk, __half* __restrict__ mv)
{
    extern __shared__ __half sm[];
    const int t = threadIdx.x;
    const int wg = t >> 8;
    const int wt = t & 255;
    __half* buf = sm + wg * 32 * KPAD;
    __half* WS = sm + 64 * KPAD;
    const int lane = t & 31;
    const int wiw = wt >> 5;
    const int mw = wiw & 1, nw = wiw >> 1;
    const int ar = mw * 16, nc0 = nw * 32;
    const int barid = 1 + wg;

    const uint32 a_base = (uint32)__cvta_generic_to_shared(buf);
    const int lrow = lane & 7, quad = lane >> 3;
    const uint32 a_off =
        ((uint32)(ar + lrow + ((quad & 1) << 3)) * KPAD + ((quad & 2) << 2)) * 2;
    const uint32 b_krow = (lane & 7) + (lane & 8);

    stage_W_512(Wq, WS + 0 * 128 * KPAD, t);
    stage_W_512(W1, WS + 1 * 128 * KPAD, t);
    stage_W_512(W2, WS + 2 * 128 * KPAD, t);
    stage_W_512(W3, WS + 3 * 128 * KPAD, t);
    stage_W_512(Wk, WS + 4 * 128 * KPAD, t);
    stage_W_512(Wv, WS + 5 * 128 * KPAD, t);
    uint32 wb[6];
#pragma unroll
    for (int i = 0; i < 6; i++)
        wb[i] = (uint32)__cvta_generic_to_shared(WS + i * 128 * KPAD);
    __syncthreads();

    float acc[4][4];
#pragma unroll 1
    for (int round = 0; round < 2; round++) {
        const long tile = (long)blockIdx.x * 2 + wg + 296 * round;
        if (tile >= 512) break;
        const long row0 = tile * 32;

#pragma unroll
        for (int i = 0; i < 4; i++) {
            int idx = wt + i * 256;
            int r = idx >> 5, c4 = idx & 31;
            float4 v = *(const float4*)(F + (row0 + r) * 128 + c4 * 4);
            uint2 raw = make_uint2(
                h2u(__float22half2_rn(make_float2(v.x, v.y))),
                h2u(__float22half2_rn(make_float2(v.z, v.w))));
            *(uint2*)(buf + r * KPAD + c4 * 4) = raw;
        }
        NBAR();

        tile_mma(a_base, wb[0], a_off, b_krow, nc0, acc);
        epi_gmem_f(acc, bq, row0, q, ar, nc0, lane);
        NBAR();

        {
            const __half2 z2 = __float2half2_rn(0.f);
#pragma unroll
            for (int i = 0; i < 2; i++) {
                int idx = wt + i * 256;
                int r = idx >> 4, c8 = idx & 15;
                __half2* p = (__half2*)(buf + r * KPAD + c8 * 8);
                p[0] = __hmax2(p[0], z2);
                p[1] = __hmax2(p[1], z2);
                p[2] = __hmax2(p[2], z2);
                p[3] = __hmax2(p[3], z2);
            }
        }
        NBAR();

        tile_mma(a_base, wb[1], a_off, b_krow, nc0, acc);
        NBAR();
        epi_smem<1, 0>(acc, b1, nullptr, row0, buf, ar, nc0, lane);
        NBAR();

        tile_mma(a_base, wb[2], a_off, b_krow, nc0, acc);
        NBAR();
        epi_smem<1, 0>(acc, b2, nullptr, row0, buf, ar, nc0, lane);
        NBAR();

        tile_mma(a_base, wb[3], a_off, b_krow, nc0, acc);
        NBAR();
        epi_smem<1, 1>(acc, b3, enc, row0, buf, ar, nc0, lane);
        NBAR();

        tile_mma(a_base, wb[4], a_off, b_krow, nc0, acc);
        epi_gmem_h(acc, row0, mk, ar, nc0, lane);
        tile_mma(a_base, wb[5], a_off, b_krow, nc0, acc);
        epi_gmem_h(acc, row0, mv, ar, nc0, lane);
        NBAR();
    }
}

// ------- out-projection (R15-proven, unchanged) -----------------------------
__global__ __launch_bounds__(256) void tgemm_out(
    const __half* __restrict__ A, const float* __restrict__ W,
    const float* __restrict__ bias, const float* __restrict__ add,
    float* __restrict__ C)
{
    extern __shared__ __half sm[];
    __half* As = sm;
    __half* Ws = sm + 32 * KPAD;
    const int t = threadIdx.x;
    const int lane = t & 31, w = t >> 5;
    const int mw = w & 1, nw = w >> 1;
    const long row0 = (long)blockIdx.x * 32;

#pragma unroll
    for (int i = 0; i < 2; i++) {
        int idx = t + i * 256;
        int r = idx >> 4, c8 = idx & 15;
        uint4 v = *(const uint4*)(A + (row0 + r) * 128 + c8 * 8);
        *(uint4*)(As + r * KPAD + c8 * 8) = v;
    }
    stage_W_256(W, Ws, t);
    __syncthreads();

    const int ar = mw * 16, nc0 = nw * 32;
    const uint32 a_base = (uint32)__cvta_generic_to_shared(As);
    const uint32 w_base = (uint32)__cvta_generic_to_shared(Ws);
    const int lrow = lane & 7, quad = lane >> 3;
    const uint32 a_off =
        ((uint32)(ar + lrow + ((quad & 1) << 3)) * KPAD + ((quad & 2) << 2)) * 2;
    const uint32 b_krow = (lane & 7) + (lane & 8);

    float acc[4][4];
    tile_mma(a_base, w_base, a_off, b_krow, nc0, acc);

    const int g = lane >> 2, tig = lane & 3;
#pragma unroll
    for (int nt = 0; nt < 4; nt++) {
        int col = nc0 + nt * 8 + tig * 2;
        long r0 = row0 + ar + g, r1 = r0 + 8;
        float2 bz = *(const float2*)(bias + col);
        float2 a0 = *(const float2*)(add + r0 * 128 + col);
        float2 a1 = *(const float2*)(add + r1 * 128 + col);
        *(float2*)(C + r0 * 128 + col) =
            make_float2(acc[nt][0] + bz.x + a0.x, acc[nt][1] + bz.y + a0.y);
        *(float2*)(C + r1 * 128 + col) =
            make_float2(acc[nt][2] + bz.x + a1.x, acc[nt][3] + bz.y + a1.y);
    }
}

// ---------------- attention: R15 structure + depth-4 rolling prefetch ------
struct __align__(16) NodeSmem {
    __half dist[32 * 36];
    __half seq[32 * 20];
    float ud_t[32 * 8];
    float us_t[16 * 8];
    float c0[8];
    float lgk[32 * 10];
    float sd[2][256];
    float ss[2][128];
    float accp[2][128];
    int   jb[32];
};

__global__ __launch_bounds__(128) void attn_kernel(
    const float* __restrict__ dist_g, const float* __restrict__ seq_g,
    const int* __restrict__ idx, const float* __restrict__ qg,
    const __half* __restrict__ mkh, const __half* __restrict__ mvh,
    const float* __restrict__ Wk, const float* __restrict__ bk,
    const float* __restrict__ Wv, const float* __restrict__ bv,
    __half* __restrict__ att_out)
{
    __shared__ NodeSmem S[2];
    const int lane = threadIdx.x & 31;
    const int w = threadIdx.x >> 5;
    const int half = w & 1;
    NodeSmem& s = S[w >> 1];
    const int n = blockIdx.x * 2 + (w >> 1);

    const float4 qv = ((const float4*)(qg + (long)n * 128))[lane];

    // ---- Phase A: staging (jb by half0; dist/seq split)
    if (half == 0) {
        s.jb[lane] = idx[n * 32 + lane];
        const float4* dg = (const float4*)(dist_g + (long)n * 1024);
#pragma unroll
        for (int it = 0; it < 4; it++) {
            int i4 = it * 32 + lane;
            float4 v = dg[i4];
            uint2 h;
            h.x = h2u(__float22half2_rn(make_float2(v.x, v.y)));
            h.y = h2u(__float22half2_rn(make_float2(v.z, v.w)));
            *(uint2*)(s.dist + (i4 >> 3) * 36 + (i4 & 7) * 4) = h;
        }
    } else {
        const float4* dg = (const float4*)(dist_g + (long)n * 1024);
#pragma unroll
        for (int it = 4; it < 8; it++) {
            int i4 = it * 32 + lane;
            float4 v = dg[i4];
            uint2 h;
            h.x = h2u(__float22half2_rn(make_float2(v.x, v.y)));
            h.y = h2u(__float22half2_rn(make_float2(v.z, v.w)));
            *(uint2*)(s.dist + (i4 >> 3) * 36 + (i4 & 7) * 4) = h;
        }
        const float4* sg = (const float4*)(seq_g + (long)n * 512);
#pragma unroll
        for (int it = 0; it < 4; it++) {
            int i4 = it * 32 + lane;
            float4 v = sg[i4];
            uint2 h;
            h.x = h2u(__float22half2_rn(make_float2(v.x, v.y)));
            h.y = h2u(__float22half2_rn(make_float2(v.z, v.w)));
            *(uint2*)(s.seq + (i4 >> 2) * 20 + (i4 & 3) * 4) = h;
        }
    }
    __syncthreads();   // jb + dist + seq visible to both warps

    // ---- depth-4 mk preload (8 regs; latency hidden by the Wk fold below)
    uint2 mkp[4];
#pragma unroll
    for (int i = 0; i < 4; i++) {
        int j = s.jb[half * 16 + i];
        mkp[i] = *(const uint2*)(mkh + (long)j * 128 + lane * 4);
    }

    // ---- Phase B: fold rows split 24/24 (+bias on half 0)
    const int h4 = lane >> 2;
#pragma unroll 8
    for (int rr = 0; rr < 24; rr++) {
        int r = half * 24 + rr;
        float4 wv = *(const float4*)(Wk + (long)(128 + r) * 128 + lane * 4);
        float p = wv.x * qv.x + wv.y * qv.y + wv.z * qv.z + wv.w * qv.w;
        p += __shfl_xor_sync(~0u, p, 1);
        p += __shfl_xor_sync(~0u, p, 2);
        if ((lane & 3) == 0) {
            if (r < 32) s.ud_t[r * 8 + h4] = p;
            else        s.us_t[(r - 32) * 8 + h4] = p;
        }
    }
    if (half == 0) {
        float4 wv = *(const float4*)(bk + lane * 4);
        float p = wv.x * qv.x + wv.y * qv.y + wv.z * qv.z + wv.w * qv.w;
        p += __shfl_xor_sync(~0u, p, 1);
        p += __shfl_xor_sync(~0u, p, 2);
        if ((lane & 3) == 0) s.c0[h4] = p;
    }

    // ---- Phase C1: rolling consume/refill of mk rows
#pragma unroll
    for (int kk = 0; kk < 16; kk++) {
        uint2 cur = mkp[kk & 3];
        if (kk < 12) {
            int j = s.jb[half * 16 + kk + 4];
            mkp[kk & 3] = *(const uint2*)(mkh + (long)j * 128 + lane * 4);
        }
        int k = half * 16 + kk;
        float2 f0 = __half22float2(*(__half2*)&cur.x);
        float2 f1 = __half22float2(*(__half2*)&cur.y);
        float p = f0.x * qv.x + f0.y * qv.y + f1.x * qv.z + f1.y * qv.w;
        p += __shfl_xor_sync(~0u, p, 1);
        p += __shfl_xor_sync(~0u, p, 2);
        if ((lane & 3) == 0) s.lgk[k * 10 + h4] = p;
    }

    // ---- depth-4 mv preload (needs only jb; overlaps sync + C2 math)
    uint2 mvp[4];
#pragma unroll
    for (int i = 0; i < 4; i++) {
        int j = s.jb[half * 16 + i];
        mvp[i] = *(const uint2*)(mvh + (long)j * 128 + lane * 4);
    }
    __syncthreads();   // lgk (mk part) + ud_t/us_t/c0 visible

    // ---- Phase C2 + softmax: each warp owns 4 heads
    {
        ull acc01 = 0ull, acc23 = 0ull;
        const __half* drow = s.dist + lane * 36;
#pragma unroll
        for (int i = 0; i < 8; i++) {
            uint2 hv = *(const uint2*)(drow + i * 4);
            float2 f0 = __half22float2(*(__half2*)&hv.x);
            float2 f1 = __half22float2(*(__half2*)&hv.y);
            float dv[4] = {f0.x, f0.y, f1.x, f1.y};
#pragma unroll
            for (int e = 0; e < 4; e++) {
                int d = i * 4 + e;
                ull dv2 = pack2(dv[e], dv[e]);
                const ull* u = (const ull*)(s.ud_t + d * 8 + half * 4);
                acc01 = ffma2(u[0], dv2, acc01);
                acc23 = ffma2(u[1], dv2, acc23);
            }
        }
        const __half* srow = s.seq + lane * 20;
#pragma unroll
        for (int i = 0; i < 4; i++) {
            uint2 hv = *(const uint2*)(srow + i * 4);
            float2 f0 = __half22float2(*(__half2*)&hv.x);
            float2 f1 = __half22float2(*(__half2*)&hv.y);
            float sv[4] = {f0.x, f0.y, f1.x, f1.y};
#pragma unroll
            for (int e = 0; e < 4; e++) {
                int si = i * 4 + e;
                ull sv2 = pack2(sv[e], sv[e]);
                const ull* u = (const ull*)(s.us_t + si * 8 + half * 4);
                acc01 = ffma2(u[0], sv2, acc01);
                acc23 = ffma2(u[1], sv2, acc23);
            }
        }
        float2 pA = unpack2(acc01), pB = unpack2(acc23);
        float pa[4] = {pA.x, pA.y, pB.x, pB.y};
#pragma unroll
        for (int hh = 0; hh < 4; hh++) {
            int h = half * 4 + hh;
            float lg = 0.25f * (s.lgk[lane * 10 + h] + pa[hh] + s.c0[h]);
            float m = lg;
#pragma unroll
            for (int o = 16; o > 0; o >>= 1)
                m = fmaxf(m, __shfl_xor_sync(~0u, m, o));
            float e = __expf(lg - m);
            float sm = e;
#pragma unroll
            for (int o = 16; o > 0; o >>= 1)
                sm += __shfl_xor_sync(~0u, sm, o);
            s.lgk[lane * 10 + h] = __fdividef(e, sm);
        }
    }
    __syncthreads();   // all attn weights final

    // ---- Phase D: rolling consume/refill of mv rows + weighted sums
    {
        const int sidx = lane & 15;
        float4 acc = make_float4(0.f, 0.f, 0.f, 0.f);
        ull sdl2[4] = {0ull, 0ull, 0ull, 0ull};
        float ssl[4] = {0.f, 0.f, 0.f, 0.f};
#pragma unroll
        for (int kk = 0; kk < 16; kk++) {
            uint2 cur = mvp[kk & 3];
            if (kk < 12) {
                int j = s.jb[half * 16 + kk + 4];
                mvp[kk & 3] = *(const uint2*)(mvh + (long)j * 128 + lane * 4);
            }
            int k = half * 16 + kk;
            float a = s.lgk[k * 10 + h4];
            float2 f0 = __half22float2(*(__half2*)&cur.x);
            float2 f1 = __half22float2(*(__half2*)&cur.y);
            acc.x += a * f0.x; acc.y += a * f0.y;
            acc.z += a * f1.x; acc.w += a * f1.y;
            float dv = __half2float(s.dist[k * 36 + lane]);
            ull dv2 = pack2(dv, dv);
            const ull* ap = (const ull*)(s.lgk + k * 10);
#pragma unroll
            for (int r = 0; r < 4; r++) sdl2[r] = ffma2(ap[r], dv2, sdl2[r]);
            float sv = __half2float(s.seq[k * 20 + sidx]);
#pragma unroll
            for (int r = 0; r < 4; r++) {
                int h2 = (lane >> 4) + 2 * r;
                ssl[r] += s.lgk[k * 10 + h2] * sv;
            }
        }
        *(float4*)(s.accp[half] + lane * 4) = acc;
#pragma unroll
        for (int r = 0; r < 4; r++) {
            float2 p = unpack2(sdl2[r]);
            s.sd[half][(2 * r) * 32 + lane] = p.x;
            s.sd[half][(2 * r + 1) * 32 + lane] = p.y;
        }
#pragma unroll
        for (int r = 0; r < 4; r++) s.ss[half][lane + 32 * r] = ssl[r];
    }
    __syncthreads();

    // ---- Phase D2: combine + project; this warp owns dims [half*64, +64)
    {
        const int i0 = half * 64 + lane * 2;
        const int h = i0 >> 4;
        float2 a0 = *(const float2*)(s.accp[0] + i0);
        float2 a1 = *(const float2*)(s.accp[1] + i0);
        float2 bb = *(const float2*)(bv + i0);
        ull o = pack2(a0.x + a1.x + bb.x, a0.y + a1.y + bb.y);
#pragma unroll 8
        for (int d = 0; d < 32; d++) {
            float sdv = s.sd[0][h * 32 + d] + s.sd[1][h * 32 + d];
            ull wv = *(const ull*)(Wv + (long)(128 + d) * 128 + i0);
            o = ffma2(wv, pack2(sdv, sdv), o);
        }
#pragma unroll 8
        for (int j2 = 0; j2 < 16; j2++) {
            int si = (h & 1) * 16 + j2 + 32 * (h >> 1);
            float ssv = s.ss[0][si] + s.ss[1][si];
            ull wv = *(const ull*)(Wv + (long)(160 + j2) * 128 + i0);
            o = ffma2(wv, pack2(ssv, ssv), o);
        }
        float2 po = unpack2(o);
        *(__half2*)(att_out + (long)n * 128 + i0) = __float22half2_rn(po);
    }
}

// ---------------- launch ----------------
#define TG_SMEM ((32 + 128) * KPAD * 2)            // 43,520 B
#define PERS_SMEM ((64 + 6 * 128) * KPAD * 2)      // 226,304 B

extern "C" void kernel_launch(void* const* d_in, const int* in_sizes, int n_in,
                              void* d_out, int out_size)
{
    const float* features = (const float*)d_in[0];
    const float* distances = (const float*)d_in[1];
    const float* sequence = (const float*)d_in[2];
    const float* encoder = (const float*)d_in[3];
    const int*   idx = (const int*)d_in[4];
    const float* W1 = (const float*)d_in[5];
    const float* b1 = (const float*)d_in[6];
    const float* W2 = (const float*)d_in[7];
    const float* b2 = (const float*)d_in[8];
    const float* W3 = (const float*)d_in[9];
    const float* b3 = (const float*)d_in[10];
    const float* Wq = (const float*)d_in[11];
    const float* bq = (const float*)d_in[12];
    const float* Wk = (const float*)d_in[13];
    const float* bk = (const float*)d_in[14];
    const float* Wv = (const float*)d_in[15];
    const float* bv = (const float*)d_in[16];
    const float* Wo = (const float*)d_in[17];
    const float* bo = (const float*)d_in[18];

    float *q;
    __half *mk, *mv, *att;
    cudaGetSymbolAddress((void**)&q, g_q);
    cudaGetSymbolAddress((void**)&mk, g_mk);
    cudaGetSymbolAddress((void**)&mv, g_mv);
    cudaGetSymbolAddress((void**)&att, g_att);

    static int smem_set = 0;
    if (!smem_set) {
        cudaFuncSetAttribute(mlp_persistent,
            cudaFuncAttributeMaxDynamicSharedMemorySize, PERS_SMEM);
        smem_set = 1;
    }

    mlp_persistent<<<148, 512, PERS_SMEM>>>(features, Wq, bq, W1, b1,
                                            W2, b2, W3, b3, encoder,
                                            Wk, Wv, q, mk, mv);
    attn_kernel<<<N_NODES / 2, 128>>>(distances, sequence, idx,
                                      q, mk, mv, Wk, bk, Wv, bv, att);
    tgemm_out<<<N_NODES / 32, 256, TG_SMEM>>>(att, Wo, bo, features,
                                              (float*)d_out);
}